// round 9
// baseline (speedup 1.0000x reference)
#include <cuda_runtime.h>

// LatentODE2 R9: R8 (E=8/warp, 1-warp CTAs, f32x2, approx-tanh, zx/p hoists)
// plus bf16 COMMUNICATION, fp32 ACCUMULATION:
//  - sW13 h-loop weights stored as 2x bf16x2 (8B/lane/k, was 16B). Unpack =
//    SHF<<16 / AND-mask on the idle ALU pipe (bf16->f32 needs no CVT).
//  - h SMEM mirror stored as bf16 uint4 row (16B for 8 elems, was 32B).
//    Register h stays fp32 (master copy) -> no accumulation drift.
// Crossbar per warp-step: ~480 -> ~350 cyc (weights 128->64, h-bcast 128->64).

#define T_STEPS 100
#define D_IN    16
#define H_DIM   32
#define HD_DIM  50
#define EULER   10
#define STEP_F  0.1f
#define DTS_F   (1.0f / 24.0f)

#define E       8
#define GRID    1024        // 8192 / 8, 32-thread CTAs

typedef unsigned long long u64;
typedef unsigned int u32;

__device__ __forceinline__ u64 pk2(float lo, float hi) {
    u64 r; asm("mov.b64 %0, {%1, %2};" : "=l"(r) : "f"(lo), "f"(hi)); return r;
}
__device__ __forceinline__ void up2(u64 v, float& a, float& b) {
    asm("mov.b64 {%0, %1}, %2;" : "=f"(a), "=f"(b) : "l"(v));
}
__device__ __forceinline__ void fma2(u64& d, u64 a, u64 b) {
    asm("fma.rn.f32x2 %0, %1, %2, %0;" : "+l"(d) : "l"(a), "l"(b));
}
__device__ __forceinline__ float tanh_fast(float v) {
    float r; asm("tanh.approx.f32 %0, %1;" : "=f"(r) : "f"(v)); return r;
}
__device__ __forceinline__ u64 tanh2(u64 v) {
    float a, b; up2(v, a, b);
    return pk2(tanh_fast(a), tanh_fast(b));
}

// Pack two f32 into bf16x2: hi half = first arg, lo half = second arg.
__device__ __forceinline__ u32 pkbf(float hi, float lo) {
    u32 r; asm("cvt.rn.bf16x2.f32 %0, %1, %2;" : "=r"(r) : "f"(hi), "f"(lo)); return r;
}
// bf16x2 -> f32x2 pair (lo-half, hi-half): SHF + AND, no CVT.
__device__ __forceinline__ u64 bfup(u32 p) {
    u32 lo = p << 16;
    u32 hi = p & 0xffff0000u;
    u64 r; asm("mov.b64 %0, {%1, %2};" : "=l"(r) : "r"(lo), "r"(hi)); return r;
}
// Duplicate lo-half of bf16x2 as f32x2 (w,w).
__device__ __forceinline__ u64 bfdup_lo(u32 p) {
    u32 t = p << 16;
    u64 r; asm("mov.b64 %0, {%1, %1};" : "=l"(r) : "r"(t)); return r;
}
// Duplicate hi-half of bf16x2 as f32x2 (w,w).
__device__ __forceinline__ u64 bfdup_hi(u32 p) {
    u32 t = p & 0xffff0000u;
    u64 r; asm("mov.b64 %0, {%1, %1};" : "=l"(r) : "r"(t)); return r;
}

__global__ void __launch_bounds__(32, 7)
latentode2_kernel(const float* __restrict__ dt,
                  const float* __restrict__ x,
                  const float* __restrict__ W1, const float* __restrict__ b1,
                  const float* __restrict__ W2, const float* __restrict__ b2,
                  const float* __restrict__ W3, const float* __restrict__ b3,
                  const float* __restrict__ W4, const float* __restrict__ b4,
                  float* __restrict__ out)
{
    // sW1x[k*32+j] = (W1[j][k], W1[j+32][k])  f32 pair, k<16 (x part, amortized /10)
    // sW13b[k*32+j] = u64{ lo u32 = bf16x2(W1[j][16+k], W1[j+32][16+k]),
    //                      hi u32 = bf16x2(W3[j][k],    W3[j+32][k]) }   k<32
    __shared__ float2 sW1x[16 * 32];
    __shared__ u64    sW13b[32 * 32];
    // x rows: A = elems 0..3 (two f32x2), B = elems 4..7.
    __shared__ ulonglong2 sXA[D_IN], sXB[D_IN];
    // h rows: bf16, 8 elems in one uint4 (e0..e7, pairs (e0,e1)(e2,e3)(e4,e5)(e6,e7)).
    __shared__ uint4 sHp[H_DIM];
    // z rows: fp32 (dh-loop precision), split A/B as before.
    __shared__ ulonglong2 sZA[HD_DIM], sZB[HD_DIM];

    const int lane = threadIdx.x;

    for (int idx = lane; idx < 16 * 32; idx += 32) {
        int k = idx >> 5, j = idx & 31;
        float hi = (j + 32 < HD_DIM) ? W1[(j + 32) * 48 + k] : 0.0f;
        sW1x[idx] = make_float2(W1[j * 48 + k], hi);
    }
    for (int idx = lane; idx < 32 * 32; idx += 32) {
        int k = idx >> 5, j = idx & 31;
        float w1lo = W1[j * 48 + 16 + k];
        float w1hi = (j + 32 < HD_DIM) ? W1[(j + 32) * 48 + 16 + k] : 0.0f;
        float w3lo = W3[j * 32 + k];
        float w3hi = W3[(j + 32) * 32 + k];
        u32 w1p = pkbf(w1hi, w1lo);     // lo-half = w1lo, hi-half = w1hi
        u32 w3p = pkbf(w3hi, w3lo);
        sW13b[idx] = (u64)w1p | ((u64)w3p << 32);
    }

    const int e0 = blockIdx.x * E;

    // W2 row in registers (lane = output k of dh).
    float w2r[HD_DIM];
#pragma unroll
    for (int j = 0; j < HD_DIM; j++) w2r[j] = W2[lane * HD_DIM + j];

    const float b1lo = b1[lane];
    const float b1hi = (lane + 32 < HD_DIM) ? b1[lane + 32] : 0.0f;
    const u64 PB3lo = pk2(b3[lane], b3[lane]);
    const u64 PB3hi = pk2(b3[lane + 32], b3[lane + 32]);
    const float b2s = b2[lane];
    const u64 PB2 = pk2(b2s, b2s);
    const float b4v = b4[0];
    const float w4a = W4[lane];
    const float w4b = W4[lane + 32];

    // h state (8 elems, own row) fp32 in registers + bf16 SMEM mirror.
    float h0 = 0, h1 = 0, h2 = 0, h3 = 0, h4 = 0, h5 = 0, h6 = 0, h7 = 0;
    sHp[lane] = make_uint4(0u, 0u, 0u, 0u);
    __syncwarp();

    const float2* dt2 = (const float2*)dt;

#pragma unroll 1
    for (int t = 0; t < T_STEPS; t++) {
        // Stage x rows (lanes 0..15 handle feature = lane), fp32.
        if (lane < D_IN) {
            float xv[E];
#pragma unroll
            for (int e = 0; e < E; e++)
                xv[e] = x[((e0 + e) * T_STEPS + t) * D_IN + lane];
            sXA[lane] = make_ulonglong2(pk2(xv[0], xv[1]), pk2(xv[2], xv[3]));
            sXB[lane] = make_ulonglong2(pk2(xv[4], xv[5]), pk2(xv[6], xv[7]));
        }
        float cs[E];
#pragma unroll
        for (int e = 0; e < E; e++) {
            float2 d = dt2[(e0 + e) * T_STEPS + t];
            cs[e] = STEP_F * ((d.y - d.x) * DTS_F);
        }
        __syncwarp();

        // Hoisted: zx = b1 + x @ W1x^T (fp32 weights; reused for 10 steps).
        u64 zxj01 = pk2(b1lo, b1lo), zxj23 = zxj01, zxj45 = zxj01, zxj67 = zxj01;
        u64 zxk01 = pk2(b1hi, b1hi), zxk23 = zxk01, zxk45 = zxk01, zxk67 = zxk01;
#pragma unroll
        for (int k = 0; k < D_IN; k++) {
            ulonglong2 vA = sXA[k], vB = sXB[k];
            float2 w = sW1x[k * 32 + lane];
            u64 wl = pk2(w.x, w.x), wh = pk2(w.y, w.y);
            fma2(zxj01, vA.x, wl); fma2(zxj23, vA.y, wl);
            fma2(zxj45, vB.x, wl); fma2(zxj67, vB.y, wl);
            fma2(zxk01, vA.x, wh); fma2(zxk23, vA.y, wh);
            fma2(zxk45, vB.x, wh); fma2(zxk67, vB.y, wh);
        }

        // Per-lane dy partial sums across all Euler steps (y has no feedback).
        float p0 = 0, p1 = 0, p2 = 0, p3 = 0, p4 = 0, p5 = 0, p6 = 0, p7 = 0;

#pragma unroll 1
        for (int s = 0; s < EULER; s++) {
            u64 zj01 = zxj01, zj23 = zxj23, zj45 = zxj45, zj67 = zxj67;
            u64 zk01 = zxk01, zk23 = zxk23, zk45 = zxk45, zk67 = zxk67;
            u64 gj01 = PB3lo, gj23 = PB3lo, gj45 = PB3lo, gj67 = PB3lo;
            u64 gk01 = PB3hi, gk23 = PB3hi, gk45 = PB3hi, gk67 = PB3hi;

            // Fused: z1 += h @ W1h^T ; g = b3 + h @ W3^T
            // h read as bf16 (16B bcast), weights read as bf16 (8B/lane).
#pragma unroll
            for (int k = 0; k < H_DIM; k++) {
                uint4 P = sHp[k];
                u64 vA0 = bfup(P.x), vA1 = bfup(P.y);   // (e0,e1), (e2,e3)
                u64 vB0 = bfup(P.z), vB1 = bfup(P.w);   // (e4,e5), (e6,e7)
                u64 wpair = sW13b[k * 32 + lane];
                u32 w1p, w3p;
                asm("mov.b64 {%0, %1}, %2;" : "=r"(w1p), "=r"(w3p) : "l"(wpair));
                u64 w1l = bfdup_lo(w1p), w1h = bfdup_hi(w1p);
                u64 w3l = bfdup_lo(w3p), w3h = bfdup_hi(w3p);
                fma2(zj01, vA0, w1l); fma2(zj23, vA1, w1l);
                fma2(zj45, vB0, w1l); fma2(zj67, vB1, w1l);
                fma2(zk01, vA0, w1h); fma2(zk23, vA1, w1h);
                fma2(zk45, vB0, w1h); fma2(zk67, vB1, w1h);
                fma2(gj01, vA0, w3l); fma2(gj23, vA1, w3l);
                fma2(gj45, vB0, w3l); fma2(gj67, vB1, w3l);
                fma2(gk01, vA0, w3h); fma2(gk23, vA1, w3h);
                fma2(gk45, vB0, w3h); fma2(gk67, vB1, w3h);
            }

            // z = tanh(z1-pre), publish fp32 rows lane and lane+32.
            sZA[lane] = make_ulonglong2(tanh2(zj01), tanh2(zj23));
            sZB[lane] = make_ulonglong2(tanh2(zj45), tanh2(zj67));
            if (lane + 32 < HD_DIM) {
                sZA[lane + 32] = make_ulonglong2(tanh2(zk01), tanh2(zk23));
                sZB[lane + 32] = make_ulonglong2(tanh2(zk45), tanh2(zk67));
            }
            __syncwarp();   // z published; h reads of this step done

            // dy partial accumulation.
            {
                float a, b, c, d;
                up2(gj01, a, b); up2(gk01, c, d);
                p0 = fmaf(tanh_fast(a), w4a, fmaf(tanh_fast(c), w4b, p0));
                p1 = fmaf(tanh_fast(b), w4a, fmaf(tanh_fast(d), w4b, p1));
                up2(gj23, a, b); up2(gk23, c, d);
                p2 = fmaf(tanh_fast(a), w4a, fmaf(tanh_fast(c), w4b, p2));
                p3 = fmaf(tanh_fast(b), w4a, fmaf(tanh_fast(d), w4b, p3));
                up2(gj45, a, b); up2(gk45, c, d);
                p4 = fmaf(tanh_fast(a), w4a, fmaf(tanh_fast(c), w4b, p4));
                p5 = fmaf(tanh_fast(b), w4a, fmaf(tanh_fast(d), w4b, p5));
                up2(gj67, a, b); up2(gk67, c, d);
                p6 = fmaf(tanh_fast(a), w4a, fmaf(tanh_fast(c), w4b, p6));
                p7 = fmaf(tanh_fast(b), w4a, fmaf(tanh_fast(d), w4b, p7));
            }

            // dh_pre = b2 + z @ W2^T (out k = lane), W2 row in registers.
            u64 d01 = PB2, d23 = PB2, d45 = PB2, d67 = PB2;
#pragma unroll
            for (int j = 0; j < HD_DIM; j++) {
                ulonglong2 zA = sZA[j], zB = sZB[j];
                u64 wd = pk2(w2r[j], w2r[j]);
                fma2(d01, zA.x, wd); fma2(d23, zA.y, wd);
                fma2(d45, zB.x, wd); fma2(d67, zB.y, wd);
            }

            // h Euler update (fp32 master copy).
            {
                float a, b;
                up2(d01, a, b); h0 = fmaf(cs[0], tanh_fast(a), h0);
                                h1 = fmaf(cs[1], tanh_fast(b), h1);
                up2(d23, a, b); h2 = fmaf(cs[2], tanh_fast(a), h2);
                                h3 = fmaf(cs[3], tanh_fast(b), h3);
                up2(d45, a, b); h4 = fmaf(cs[4], tanh_fast(a), h4);
                                h5 = fmaf(cs[5], tanh_fast(b), h5);
                up2(d67, a, b); h6 = fmaf(cs[6], tanh_fast(a), h6);
                                h7 = fmaf(cs[7], tanh_fast(b), h7);
            }

            // Publish h as bf16 (one 16B store).
            sHp[lane] = make_uint4(pkbf(h1, h0), pkbf(h3, h2),
                                   pkbf(h5, h4), pkbf(h7, h6));
            __syncwarp();
        }

        // One butterfly reduction per t-step.
#pragma unroll
        for (int off = 16; off > 0; off >>= 1) {
            p0 += __shfl_xor_sync(0xffffffffu, p0, off);
            p1 += __shfl_xor_sync(0xffffffffu, p1, off);
            p2 += __shfl_xor_sync(0xffffffffu, p2, off);
            p3 += __shfl_xor_sync(0xffffffffu, p3, off);
            p4 += __shfl_xor_sync(0xffffffffu, p4, off);
            p5 += __shfl_xor_sync(0xffffffffu, p5, off);
            p6 += __shfl_xor_sync(0xffffffffu, p6, off);
            p7 += __shfl_xor_sync(0xffffffffu, p7, off);
        }

        // y_e = x0_e + cs_e * (P_e + EULER*b4); lanes 0..7 write out.
        {
            float x0A, x1A, x2A, x3A, x4A, x5A, x6A, x7A;
            { ulonglong2 v = sXA[0]; up2(v.x, x0A, x1A); up2(v.y, x2A, x3A); }
            { ulonglong2 v = sXB[0]; up2(v.x, x4A, x5A); up2(v.y, x6A, x7A); }
            const float eb4 = (float)EULER * b4v;
            float yv = fmaf(cs[0], p0 + eb4, x0A);
            if (lane == 1) yv = fmaf(cs[1], p1 + eb4, x1A);
            if (lane == 2) yv = fmaf(cs[2], p2 + eb4, x2A);
            if (lane == 3) yv = fmaf(cs[3], p3 + eb4, x3A);
            if (lane == 4) yv = fmaf(cs[4], p4 + eb4, x4A);
            if (lane == 5) yv = fmaf(cs[5], p5 + eb4, x5A);
            if (lane == 6) yv = fmaf(cs[6], p6 + eb4, x6A);
            if (lane == 7) yv = fmaf(cs[7], p7 + eb4, x7A);
            if (lane < E) out[(e0 + lane) * T_STEPS + t] = yv;
        }
        __syncwarp();   // sX reads done before next t overwrites
    }
}

extern "C" void kernel_launch(void* const* d_in, const int* in_sizes, int n_in,
                              void* d_out, int out_size) {
    (void)in_sizes; (void)n_in; (void)out_size;
    const float* dt = (const float*)d_in[0];
    const float* x  = (const float*)d_in[1];
    const float* W1 = (const float*)d_in[2];
    const float* b1 = (const float*)d_in[3];
    const float* W2 = (const float*)d_in[4];
    const float* b2 = (const float*)d_in[5];
    const float* W3 = (const float*)d_in[6];
    const float* b3 = (const float*)d_in[7];
    const float* W4 = (const float*)d_in[8];
    const float* b4 = (const float*)d_in[9];
    float* out = (float*)d_out;

    latentode2_kernel<<<GRID, 32>>>(
        dt, x, W1, b1, W2, b2, W3, b3, W4, b4, out);
}